// round 15
// baseline (speedup 1.0000x reference)
#include <cuda_runtime.h>
#include <cuda_fp16.h>
#include <math.h>

#define BB 128
#define TT 512
#define GW_STRIDE 2080
#define NT 512

// gate row partition: [0,768) registers fp16, [768,2048) SMEM fp16
#define RROWS 768
#define SBASE 768
#define SROWS 1280
#define HP 36                     // padded h row stride (floats)

// SMEM float offsets (sW16 = 1280*64 halves = 40960 floats)
#define OFF_H  40960              // h state [64][36] fp32
#define OFF_HD 43264              // duplicated half2 h [2048]
#define OFF_A  45312              // 4x32x32 fp32
#define OFF_P  49408              // fp16 partials [16][72] halves
#define OFF_GR 49984              // 4x64
#define OFF_X  50240              // 512 ints
#define SMEM_FLOATS 50752         // 203008 bytes

__device__ float  d_A[4096];          // A[c][j][k]
__device__ float  d_gr[256];          // gate_b + r-term, [c][d]
__device__ __half d_gw16[2048 * 64];  // transposed fp16 weights [j][d]

static __device__ __forceinline__ unsigned long long pk2(float a, float b) {
    unsigned long long r; asm("mov.b64 %0, {%1,%2};" : "=l"(r) : "f"(a), "f"(b)); return r;
}
static __device__ __forceinline__ void ffma2(unsigned long long& d,
                                             unsigned long long a, unsigned long long b) {
    asm("fma.rn.f32x2 %0, %1, %2, %0;" : "+l"(d) : "l"(a), "l"(b));
}
static __device__ __forceinline__ float2 upk2(unsigned long long v) {
    float lo, hi; asm("mov.b64 {%0,%1}, %2;" : "=f"(lo), "=f"(hi) : "l"(v));
    return make_float2(lo, hi);
}
static __device__ __forceinline__ unsigned h2u(__half2 h) { return *(unsigned*)&h; }
static __device__ __forceinline__ __half2 u2h(unsigned u) { return *(__half2*)&u; }

__global__ void setup_kernel(const float* __restrict__ emb,
                             const float* __restrict__ gate_w,
                             const float* __restrict__ gate_b,
                             const float* __restrict__ gp) {
    __shared__ float r[4][32];
    int t = threadIdx.x;           // 256 threads
    if (t < 128) {
        int c = t >> 5, i = t & 31;
        float v = emb[c * 32 + i];
        float s = v * v;
        #pragma unroll
        for (int off = 16; off; off >>= 1) s += __shfl_xor_sync(0xffffffffu, s, off);
        r[c][i] = v / (sqrtf(s) + 1e-8f);
    }
    __syncthreads();
    for (int idx = t; idx < 4096; idx += 256) {
        int cc = idx >> 10, jk = idx & 1023;
        float acc = 0.f;
        #pragma unroll
        for (int ii = 0; ii < 32; ii++) acc += r[cc][ii] * gp[ii * 1024 + jk];
        d_A[idx] = acc;
    }
    for (int idx = t; idx < 256; idx += 256) {
        int cc = idx >> 6, d = idx & 63;
        float acc = gate_b[d];
        #pragma unroll
        for (int ii = 0; ii < 32; ii++)
            acc += gate_w[d * GW_STRIDE + 2048 + ii] * r[cc][ii];
        d_gr[idx] = acc;
    }
    for (int idx = t; idx < 2048 * 64; idx += 256) {
        int j = idx >> 6, d = idx & 63;
        d_gw16[idx] = __float2half_rn(gate_w[(size_t)d * GW_STRIDE + j]);
    }
}

__global__ void __launch_bounds__(NT, 1)
versor_main_kernel(const int* __restrict__ x,
                   const float* __restrict__ w1, const float* __restrict__ b1,
                   const float* __restrict__ ln_g, const float* __restrict__ ln_b,
                   const float* __restrict__ w2, const float* __restrict__ b2,
                   float* __restrict__ out) {
    extern __shared__ float sm[];
    __half*  sW16 = (__half*)sm;              // [1280][64] fp16 (local row = j-768)
    float*   sH   = sm + OFF_H;               // h state [64][HP]
    __half2* sHd  = (__half2*)(sm + OFF_HD);  // duplicated (h,h), 2048 rows
    float*   sA   = sm + OFF_A;
    __half*  sPh  = (__half*)(sm + OFF_P);    // fp16 partials [16][72]
    float*   sGr  = sm + OFF_GR;
    int*     sX   = (int*)(sm + OFF_X);
    float*   sZ   = sm + OFF_P;               // head alias (after loop)

    const int tid  = threadIdx.x;
    const int lane = tid & 31;
    const int w    = tid >> 5;                // warp 0..15
    const int jway = lane >> 3;               // 0..3
    const int oct  = lane & 7;                // d-octet
    const int b    = blockIdx.x;
    const int grp  = w * 4 + jway;            // row group 0..63

    // ---- init SMEM ----
    for (int idx = tid; idx < SROWS * 8; idx += NT)   // 1280*64 halves as uint4
        ((uint4*)sW16)[idx] = ((const uint4*)(d_gw16 + SBASE * 64))[idx];
    for (int idx = tid; idx < 4096; idx += NT) sA[idx] = d_A[idx];
    for (int idx = tid; idx < 256;  idx += NT) sGr[idx] = d_gr[idx];
    for (int idx = tid; idx < TT;   idx += NT) sX[idx] = x[b * TT + idx];
    for (int idx = tid; idx < 64 * HP; idx += NT)
        sH[idx] = ((idx % HP) == 0) ? 1.f : 0.f;
    for (int idx = tid; idx < 2048; idx += NT)
        sHd[idx] = __floats2half2_rn(((idx & 31) == 0) ? 1.f : 0.f,
                                     ((idx & 31) == 0) ? 1.f : 0.f);

    // ---- register fp16 weights: rows [0,768), 12 j x 8 d(4 half2)/thread ----
    unsigned wreg[48];
    {
        const int jb = grp * 12;
        #pragma unroll
        for (int jj = 0; jj < 12; jj++) {
            const uint4 v = *(const uint4*)(d_gw16 + (size_t)(jb + jj) * 64 + oct * 8);
            wreg[4 * jj + 0] = v.x; wreg[4 * jj + 1] = v.y;
            wreg[4 * jj + 2] = v.z; wreg[4 * jj + 3] = v.w;
        }
    }
    __syncthreads();

    const int dB = tid >> 3;              // phase-B versor (warp-exclusive row)
    const int s8 = tid & 7;               // 8-thread subgroup within versor
    const int k0 = s8 * 4;                // phase-B blade quad
    const __half2 hz = __float2half2_rn(0.f);

    int c = sX[0];
    #pragma unroll 1
    for (int t = 0; t < TT; t++) {
        const int c_next = (t + 1 < TT) ? sX[t + 1] : 0;

        // ============ Phase A: gate partial dots (all HFMA2, octet-d) ============
        __half2 ha0 = hz, ha1 = hz, ha2 = hz, ha3 = hz;
        // SMEM rows first (LSU starts immediately; reg-row FMAs overlap latency)
        {
            const int rb = grp * 20;
            #pragma unroll
            for (int q = 0; q < 5; q++) {
                const uint4 hq = *(const uint4*)(sHd + SBASE + rb + 4 * q);
                const __half2 hh[4] = { u2h(hq.x), u2h(hq.y), u2h(hq.z), u2h(hq.w) };
                #pragma unroll
                for (int rr = 0; rr < 4; rr++) {
                    const uint4 wv = ((const uint4*)sW16)[(rb + 4 * q + rr) * 8 + oct];
                    ha0 = __hfma2(u2h(wv.x), hh[rr], ha0);
                    ha1 = __hfma2(u2h(wv.y), hh[rr], ha1);
                    ha2 = __hfma2(u2h(wv.z), hh[rr], ha2);
                    ha3 = __hfma2(u2h(wv.w), hh[rr], ha3);
                }
            }
        }
        // register rows (12)
        {
            const int jb = grp * 12;
            #pragma unroll
            for (int q = 0; q < 3; q++) {
                const uint4 hq = *(const uint4*)(sHd + jb + 4 * q);
                const __half2 h0 = u2h(hq.x), h1 = u2h(hq.y);
                const __half2 h2 = u2h(hq.z), h3 = u2h(hq.w);
                ha0 = __hfma2(u2h(wreg[16 * q + 0]),  h0, ha0);
                ha1 = __hfma2(u2h(wreg[16 * q + 1]),  h0, ha1);
                ha2 = __hfma2(u2h(wreg[16 * q + 2]),  h0, ha2);
                ha3 = __hfma2(u2h(wreg[16 * q + 3]),  h0, ha3);
                ha0 = __hfma2(u2h(wreg[16 * q + 4]),  h1, ha0);
                ha1 = __hfma2(u2h(wreg[16 * q + 5]),  h1, ha1);
                ha2 = __hfma2(u2h(wreg[16 * q + 6]),  h1, ha2);
                ha3 = __hfma2(u2h(wreg[16 * q + 7]),  h1, ha3);
                ha0 = __hfma2(u2h(wreg[16 * q + 8]),  h2, ha0);
                ha1 = __hfma2(u2h(wreg[16 * q + 9]),  h2, ha1);
                ha2 = __hfma2(u2h(wreg[16 * q + 10]), h2, ha2);
                ha3 = __hfma2(u2h(wreg[16 * q + 11]), h2, ha3);
                ha0 = __hfma2(u2h(wreg[16 * q + 12]), h3, ha0);
                ha1 = __hfma2(u2h(wreg[16 * q + 13]), h3, ha1);
                ha2 = __hfma2(u2h(wreg[16 * q + 14]), h3, ha2);
                ha3 = __hfma2(u2h(wreg[16 * q + 15]), h3, ha3);
            }
        }
        // reduce across the 4 jways, store RAW fp16 partials
        {
            #pragma unroll
            for (int off = 8; off <= 16; off <<= 1) {
                ha0 = __hadd2(ha0, u2h(__shfl_xor_sync(0xffffffffu, h2u(ha0), off)));
                ha1 = __hadd2(ha1, u2h(__shfl_xor_sync(0xffffffffu, h2u(ha1), off)));
                ha2 = __hadd2(ha2, u2h(__shfl_xor_sync(0xffffffffu, h2u(ha2), off)));
                ha3 = __hadd2(ha3, u2h(__shfl_xor_sync(0xffffffffu, h2u(ha3), off)));
            }
            if (jway == 0) {
                uint4 pk;
                pk.x = h2u(ha0); pk.y = h2u(ha1); pk.z = h2u(ha2); pk.w = h2u(ha3);
                *(uint4*)(sPh + w * 72 + oct * 8) = pk;
            }
        }

        // ---- geometric product (pre-barrier; h stable, rows warp-exclusive) ----
        float2 na, nb;
        float4 hq4;
        float hn, nn;
        {
            unsigned long long n0 = 0ull, n1 = 0ull;
            const float* hrow = sH + dB * HP;
            const ulonglong2* Ap = (const ulonglong2*)(sA + c * 1024) + s8;
            #pragma unroll
            for (int jq = 0; jq < 8; jq++) {
                const float4 hv = *(const float4*)(hrow + jq * 4);
                unsigned long long hp; ulonglong2 av;
                hp = pk2(hv.x, hv.x); av = Ap[(jq * 4 + 0) * 8];
                ffma2(n0, av.x, hp); ffma2(n1, av.y, hp);
                hp = pk2(hv.y, hv.y); av = Ap[(jq * 4 + 1) * 8];
                ffma2(n0, av.x, hp); ffma2(n1, av.y, hp);
                hp = pk2(hv.z, hv.z); av = Ap[(jq * 4 + 2) * 8];
                ffma2(n0, av.x, hp); ffma2(n1, av.y, hp);
                hp = pk2(hv.w, hv.w); av = Ap[(jq * 4 + 3) * 8];
                ffma2(n0, av.x, hp); ffma2(n1, av.y, hp);
            }
            hq4 = *(const float4*)(hrow + k0);
            na = upk2(n0); nb = upk2(n1);
            // pre-barrier reductions for the algebraic norm: h.n and |n|^2
            hn = hq4.x * na.x + hq4.y * na.y + hq4.z * nb.x + hq4.w * nb.y;
            nn = na.x * na.x + na.y * na.y + nb.x * nb.x + nb.y * nb.y;
            hn += __shfl_xor_sync(0xffffffffu, hn, 1);
            nn += __shfl_xor_sync(0xffffffffu, nn, 1);
            hn += __shfl_xor_sync(0xffffffffu, hn, 2);
            nn += __shfl_xor_sync(0xffffffffu, nn, 2);
            hn += __shfl_xor_sync(0xffffffffu, hn, 4);
            nn += __shfl_xor_sync(0xffffffffu, nn, 4);
        }
        __syncthreads();   // barrier 1: partials visible; phase-A sHd reads done

        // ---- distributed gate reduce: 8 threads per versor ----
        float g;
        {
            float s = __half2float(sPh[(2 * s8) * 72 + dB])
                    + __half2float(sPh[(2 * s8 + 1) * 72 + dB]);
            s += __shfl_xor_sync(0xffffffffu, s, 1);
            s += __shfl_xor_sync(0xffffffffu, s, 2);
            s += __shfl_xor_sync(0xffffffffu, s, 4);
            s += sGr[c * 64 + dB];
            g = __fdividef(1.f, 1.f + __expf(-s));
        }

        // ---- blend + algebraic normalize + store (fp32 state + dup-half2) ----
        {
            const float om = 1.f - g;
            // |v|^2 = om^2*|h|^2 + 2*g*om*(h.n) + g^2*|n|^2, with |h|^2 = 1
            const float vn2 = om * om + 2.f * g * om * hn + g * g * nn;
            const float sc = rsqrtf(vn2 + 1e-20f);
            float4 v;
            v.x = (om * hq4.x + g * na.x) * sc;
            v.y = (om * hq4.y + g * na.y) * sc;
            v.z = (om * hq4.z + g * nb.x) * sc;
            v.w = (om * hq4.w + g * nb.y) * sc;
            *(float4*)(sH + dB * HP + k0) = v;
            uint4 pd;
            pd.x = h2u(__floats2half2_rn(v.x, v.x));
            pd.y = h2u(__floats2half2_rn(v.y, v.y));
            pd.z = h2u(__floats2half2_rn(v.z, v.z));
            pd.w = h2u(__floats2half2_rn(v.w, v.w));
            *(uint4*)(sHd + dB * 32 + k0) = pd;
        }
        c = c_next;
        __syncthreads();   // barrier 2: new h (fp32 + dup) visible
    }

    // ============ Head: z = h@w1.T + b1, LN, relu, @w2.T + b2 ============
    #pragma unroll 1
    for (int rr = 0; rr < 8; rr++) {
        const int r = w * 8 + rr;
        float a = 0.f;
        #pragma unroll 4
        for (int ch = 0; ch < 16; ch++) {
            const int j = ch * 128 + lane * 4;
            const float4 hv = *(const float4*)(sH + (j >> 5) * HP + (j & 31));
            const float4 wv = *(const float4*)(w1 + (size_t)r * 2048 + j);
            a = fmaf(wv.x, hv.x, fmaf(wv.y, hv.y,
                fmaf(wv.z, hv.z, fmaf(wv.w, hv.w, a))));
        }
        #pragma unroll
        for (int off = 16; off; off >>= 1) a += __shfl_xor_sync(0xffffffffu, a, off);
        if (lane == 0) sZ[r] = a + __ldg(b1 + r);
    }
    __syncthreads();
    if (w == 0) {
        float zv[4];
        #pragma unroll
        for (int qq = 0; qq < 4; qq++) zv[qq] = sZ[lane + 32 * qq];
        float s1 = zv[0] + zv[1] + zv[2] + zv[3];
        float s2 = zv[0] * zv[0] + zv[1] * zv[1] + zv[2] * zv[2] + zv[3] * zv[3];
        #pragma unroll
        for (int off = 16; off; off >>= 1) {
            s1 += __shfl_xor_sync(0xffffffffu, s1, off);
            s2 += __shfl_xor_sync(0xffffffffu, s2, off);
        }
        const float mu  = s1 * (1.f / 128.f);
        const float var = s2 * (1.f / 128.f) - mu * mu;
        const float rs  = __fdividef(1.f, sqrtf(var + 1e-5f));
        float o0 = 0.f, o1 = 0.f;
        #pragma unroll
        for (int qq = 0; qq < 4; qq++) {
            const int r = lane + 32 * qq;
            float zn = (zv[qq] - mu) * rs * __ldg(ln_g + r) + __ldg(ln_b + r);
            zn = fmaxf(zn, 0.f);
            o0 = fmaf(zn, __ldg(w2 + r), o0);
            o1 = fmaf(zn, __ldg(w2 + 128 + r), o1);
        }
        #pragma unroll
        for (int off = 16; off; off >>= 1) {
            o0 += __shfl_xor_sync(0xffffffffu, o0, off);
            o1 += __shfl_xor_sync(0xffffffffu, o1, off);
        }
        if (lane == 0) {
            out[b * 2 + 0] = o0 + __ldg(b2 + 0);
            out[b * 2 + 1] = o1 + __ldg(b2 + 1);
        }
    }
}

extern "C" void kernel_launch(void* const* d_in, const int* in_sizes, int n_in,
                              void* d_out, int out_size) {
    const int*   x      = (const int*)  d_in[0];
    const float* emb    = (const float*)d_in[1];
    const float* gate_w = (const float*)d_in[2];
    const float* gate_b = (const float*)d_in[3];
    const float* w1     = (const float*)d_in[4];
    const float* b1     = (const float*)d_in[5];
    const float* ln_g   = (const float*)d_in[6];
    const float* ln_b   = (const float*)d_in[7];
    const float* w2     = (const float*)d_in[8];
    const float* b2     = (const float*)d_in[9];
    const float* gp     = (const float*)d_in[10];
    float* out = (float*)d_out;

    setup_kernel<<<1, 256>>>(emb, gate_w, gate_b, gp);

    const int smem_bytes = SMEM_FLOATS * 4;
    cudaFuncSetAttribute(versor_main_kernel,
                         cudaFuncAttributeMaxDynamicSharedMemorySize, smem_bytes);
    versor_main_kernel<<<BB, NT, smem_bytes>>>(x, w1, b1, ln_g, ln_b, w2, b2, out);
}

// round 16
// speedup vs baseline: 1.0460x; 1.0460x over previous
#include <cuda_runtime.h>
#include <cuda_fp16.h>
#include <math.h>

#define BB 128
#define TT 512
#define GW_STRIDE 2080
#define NT 512

// gate row partition: [0,768) registers fp16, [768,2048) SMEM fp16
#define RROWS 768
#define SBASE 768
#define SROWS 1280
#define HP 36                     // padded h row stride (floats)

// SMEM float offsets (sW16 = 1280*64 halves = 40960 floats)
#define OFF_H  40960              // h state [64][36] fp32
#define OFF_HD 43264              // duplicated half2 h [2048]
#define OFF_A  45312              // 4x32x32 fp32
#define OFF_P  49408              // fp16 partials [16][72] halves
#define OFF_GR 49984              // 4x64
#define OFF_X  50240              // 512 ints
#define SMEM_FLOATS 50752         // 203008 bytes

__device__ float  d_A[4096];          // A[c][j][k]
__device__ float  d_gr[256];          // gate_b + r-term, [c][d]
__device__ __half d_gw16[2048 * 64];  // transposed fp16 weights [j][d]

static __device__ __forceinline__ unsigned long long pk2(float a, float b) {
    unsigned long long r; asm("mov.b64 %0, {%1,%2};" : "=l"(r) : "f"(a), "f"(b)); return r;
}
static __device__ __forceinline__ void ffma2(unsigned long long& d,
                                             unsigned long long a, unsigned long long b) {
    asm("fma.rn.f32x2 %0, %1, %2, %0;" : "+l"(d) : "l"(a), "l"(b));
}
static __device__ __forceinline__ float2 upk2(unsigned long long v) {
    float lo, hi; asm("mov.b64 {%0,%1}, %2;" : "=f"(lo), "=f"(hi) : "l"(v));
    return make_float2(lo, hi);
}
static __device__ __forceinline__ unsigned h2u(__half2 h) { return *(unsigned*)&h; }
static __device__ __forceinline__ __half2 u2h(unsigned u) { return *(__half2*)&u; }

__global__ void setup_kernel(const float* __restrict__ emb,
                             const float* __restrict__ gate_w,
                             const float* __restrict__ gate_b,
                             const float* __restrict__ gp) {
    __shared__ float r[4][32];
    int t = threadIdx.x;           // 256 threads
    if (t < 128) {
        int c = t >> 5, i = t & 31;
        float v = emb[c * 32 + i];
        float s = v * v;
        #pragma unroll
        for (int off = 16; off; off >>= 1) s += __shfl_xor_sync(0xffffffffu, s, off);
        r[c][i] = v / (sqrtf(s) + 1e-8f);
    }
    __syncthreads();
    for (int idx = t; idx < 4096; idx += 256) {
        int cc = idx >> 10, jk = idx & 1023;
        float acc = 0.f;
        #pragma unroll
        for (int ii = 0; ii < 32; ii++) acc += r[cc][ii] * gp[ii * 1024 + jk];
        d_A[idx] = acc;
    }
    for (int idx = t; idx < 256; idx += 256) {
        int cc = idx >> 6, d = idx & 63;
        float acc = gate_b[d];
        #pragma unroll
        for (int ii = 0; ii < 32; ii++)
            acc += gate_w[d * GW_STRIDE + 2048 + ii] * r[cc][ii];
        d_gr[idx] = acc;
    }
    for (int idx = t; idx < 2048 * 64; idx += 256) {
        int j = idx >> 6, d = idx & 63;
        d_gw16[idx] = __float2half_rn(gate_w[(size_t)d * GW_STRIDE + j]);
    }
}

__global__ void __launch_bounds__(NT, 1)
versor_main_kernel(const int* __restrict__ x,
                   const float* __restrict__ w1, const float* __restrict__ b1,
                   const float* __restrict__ ln_g, const float* __restrict__ ln_b,
                   const float* __restrict__ w2, const float* __restrict__ b2,
                   float* __restrict__ out) {
    extern __shared__ float sm[];
    __half*  sW16 = (__half*)sm;              // [1280][64] fp16 (local row = j-768)
    float*   sH   = sm + OFF_H;               // h state [64][HP]
    __half2* sHd  = (__half2*)(sm + OFF_HD);  // duplicated (h,h), 2048 rows
    float*   sA   = sm + OFF_A;
    __half*  sPh  = (__half*)(sm + OFF_P);    // fp16 partials [16][72]
    float*   sGr  = sm + OFF_GR;
    int*     sX   = (int*)(sm + OFF_X);
    float*   sZ   = sm + OFF_P;               // head alias (after loop)

    const int tid  = threadIdx.x;
    const int lane = tid & 31;
    const int w    = tid >> 5;                // warp 0..15
    const int jway = lane >> 3;               // 0..3
    const int oct  = lane & 7;                // d-octet
    const int b    = blockIdx.x;
    const int grp  = w * 4 + jway;            // row group 0..63

    // ---- init SMEM ----
    for (int idx = tid; idx < SROWS * 8; idx += NT)   // 1280*64 halves as uint4
        ((uint4*)sW16)[idx] = ((const uint4*)(d_gw16 + SBASE * 64))[idx];
    for (int idx = tid; idx < 4096; idx += NT) sA[idx] = d_A[idx];
    for (int idx = tid; idx < 256;  idx += NT) sGr[idx] = d_gr[idx];
    for (int idx = tid; idx < TT;   idx += NT) sX[idx] = x[b * TT + idx];
    for (int idx = tid; idx < 64 * HP; idx += NT)
        sH[idx] = ((idx % HP) == 0) ? 1.f : 0.f;
    for (int idx = tid; idx < 2048; idx += NT)
        sHd[idx] = __floats2half2_rn(((idx & 31) == 0) ? 1.f : 0.f,
                                     ((idx & 31) == 0) ? 1.f : 0.f);

    // ---- register fp16 weights: rows [0,768), 12 j x 8 d(4 half2)/thread ----
    unsigned wreg[48];
    {
        const int jb = grp * 12;
        #pragma unroll
        for (int jj = 0; jj < 12; jj++) {
            const uint4 v = *(const uint4*)(d_gw16 + (size_t)(jb + jj) * 64 + oct * 8);
            wreg[4 * jj + 0] = v.x; wreg[4 * jj + 1] = v.y;
            wreg[4 * jj + 2] = v.z; wreg[4 * jj + 3] = v.w;
        }
    }
    __syncthreads();

    const int dB = tid >> 3;              // phase-B versor (warp-exclusive row)
    const int s8 = tid & 7;               // 8-thread subgroup within versor
    const int k0 = s8 * 4;                // phase-B blade quad
    const __half2 hz = __float2half2_rn(0.f);

    int c = sX[0];
    #pragma unroll 1
    for (int t = 0; t < TT; t++) {
        const int c_next = (t + 1 < TT) ? sX[t + 1] : 0;

        // ============ Phase A: gate partial dots (all HFMA2, octet-d) ============
        __half2 ha0 = hz, ha1 = hz, ha2 = hz, ha3 = hz;
        // register rows (12), hj via 3 x LDS.128 on dup array
        {
            const int jb = grp * 12;
            #pragma unroll
            for (int q = 0; q < 3; q++) {
                const uint4 hq = *(const uint4*)(sHd + jb + 4 * q);
                const __half2 h0 = u2h(hq.x), h1 = u2h(hq.y);
                const __half2 h2 = u2h(hq.z), h3 = u2h(hq.w);
                ha0 = __hfma2(u2h(wreg[16 * q + 0]),  h0, ha0);
                ha1 = __hfma2(u2h(wreg[16 * q + 1]),  h0, ha1);
                ha2 = __hfma2(u2h(wreg[16 * q + 2]),  h0, ha2);
                ha3 = __hfma2(u2h(wreg[16 * q + 3]),  h0, ha3);
                ha0 = __hfma2(u2h(wreg[16 * q + 4]),  h1, ha0);
                ha1 = __hfma2(u2h(wreg[16 * q + 5]),  h1, ha1);
                ha2 = __hfma2(u2h(wreg[16 * q + 6]),  h1, ha2);
                ha3 = __hfma2(u2h(wreg[16 * q + 7]),  h1, ha3);
                ha0 = __hfma2(u2h(wreg[16 * q + 8]),  h2, ha0);
                ha1 = __hfma2(u2h(wreg[16 * q + 9]),  h2, ha1);
                ha2 = __hfma2(u2h(wreg[16 * q + 10]), h2, ha2);
                ha3 = __hfma2(u2h(wreg[16 * q + 11]), h2, ha3);
                ha0 = __hfma2(u2h(wreg[16 * q + 12]), h3, ha0);
                ha1 = __hfma2(u2h(wreg[16 * q + 13]), h3, ha1);
                ha2 = __hfma2(u2h(wreg[16 * q + 14]), h3, ha2);
                ha3 = __hfma2(u2h(wreg[16 * q + 15]), h3, ha3);
            }
        }
        // SMEM rows (20): local rows [grp*20, grp*20+20)
        {
            const int rb = grp * 20;
            #pragma unroll
            for (int q = 0; q < 5; q++) {
                const uint4 hq = *(const uint4*)(sHd + SBASE + rb + 4 * q);
                const __half2 hh[4] = { u2h(hq.x), u2h(hq.y), u2h(hq.z), u2h(hq.w) };
                #pragma unroll
                for (int rr = 0; rr < 4; rr++) {
                    const uint4 wv = ((const uint4*)sW16)[(rb + 4 * q + rr) * 8 + oct];
                    ha0 = __hfma2(u2h(wv.x), hh[rr], ha0);
                    ha1 = __hfma2(u2h(wv.y), hh[rr], ha1);
                    ha2 = __hfma2(u2h(wv.z), hh[rr], ha2);
                    ha3 = __hfma2(u2h(wv.w), hh[rr], ha3);
                }
            }
        }
        // reduce across the 4 jways, store RAW fp16 partials (1 STS.128, no cvt)
        {
            #pragma unroll
            for (int off = 8; off <= 16; off <<= 1) {
                ha0 = __hadd2(ha0, u2h(__shfl_xor_sync(0xffffffffu, h2u(ha0), off)));
                ha1 = __hadd2(ha1, u2h(__shfl_xor_sync(0xffffffffu, h2u(ha1), off)));
                ha2 = __hadd2(ha2, u2h(__shfl_xor_sync(0xffffffffu, h2u(ha2), off)));
                ha3 = __hadd2(ha3, u2h(__shfl_xor_sync(0xffffffffu, h2u(ha3), off)));
            }
            if (jway == 0) {
                uint4 pk;
                pk.x = h2u(ha0); pk.y = h2u(ha1); pk.z = h2u(ha2); pk.w = h2u(ha3);
                *(uint4*)(sPh + w * 72 + oct * 8) = pk;
            }
        }

        // ---- geometric product (pre-barrier; h stable, rows warp-exclusive) ----
        unsigned long long n0 = 0ull, n1 = 0ull;
        float4 hq4;
        {
            const float* hrow = sH + dB * HP;
            const ulonglong2* Ap = (const ulonglong2*)(sA + c * 1024) + s8;
            #pragma unroll
            for (int jq = 0; jq < 8; jq++) {
                const float4 hv = *(const float4*)(hrow + jq * 4);
                unsigned long long hp; ulonglong2 av;
                hp = pk2(hv.x, hv.x); av = Ap[(jq * 4 + 0) * 8];
                ffma2(n0, av.x, hp); ffma2(n1, av.y, hp);
                hp = pk2(hv.y, hv.y); av = Ap[(jq * 4 + 1) * 8];
                ffma2(n0, av.x, hp); ffma2(n1, av.y, hp);
                hp = pk2(hv.z, hv.z); av = Ap[(jq * 4 + 2) * 8];
                ffma2(n0, av.x, hp); ffma2(n1, av.y, hp);
                hp = pk2(hv.w, hv.w); av = Ap[(jq * 4 + 3) * 8];
                ffma2(n0, av.x, hp); ffma2(n1, av.y, hp);
            }
            hq4 = *(const float4*)(hrow + k0);
        }
        __syncthreads();   // barrier 1: partials visible; phase-A sHd reads done

        // ---- distributed gate reduce: 8 threads per versor ----
        float g;
        {
            float s = __half2float(sPh[(2 * s8) * 72 + dB])
                    + __half2float(sPh[(2 * s8 + 1) * 72 + dB]);
            s += __shfl_xor_sync(0xffffffffu, s, 1);
            s += __shfl_xor_sync(0xffffffffu, s, 2);
            s += __shfl_xor_sync(0xffffffffu, s, 4);
            s += sGr[c * 64 + dB];
            g = __fdividef(1.f, 1.f + __expf(-s));
        }

        // ---- blend + normalize + store (fp32 state + dup-half2) ----
        {
            const float om = 1.f - g;
            const float2 na = upk2(n0);
            const float2 nb = upk2(n1);
            float4 v;
            v.x = om * hq4.x + g * na.x;
            v.y = om * hq4.y + g * na.y;
            v.z = om * hq4.z + g * nb.x;
            v.w = om * hq4.w + g * nb.y;
            float ss = v.x * v.x + v.y * v.y + v.z * v.z + v.w * v.w;
            ss += __shfl_xor_sync(0xffffffffu, ss, 1);
            ss += __shfl_xor_sync(0xffffffffu, ss, 2);
            ss += __shfl_xor_sync(0xffffffffu, ss, 4);
            const float sc = rsqrtf(ss + 1e-20f);
            v.x *= sc; v.y *= sc; v.z *= sc; v.w *= sc;
            *(float4*)(sH + dB * HP + k0) = v;
            uint4 pd;
            pd.x = h2u(__floats2half2_rn(v.x, v.x));
            pd.y = h2u(__floats2half2_rn(v.y, v.y));
            pd.z = h2u(__floats2half2_rn(v.z, v.z));
            pd.w = h2u(__floats2half2_rn(v.w, v.w));
            *(uint4*)(sHd + dB * 32 + k0) = pd;
        }
        c = c_next;
        __syncthreads();   // barrier 2: new h (fp32 + dup) visible
    }

    // ============ Head: z = h@w1.T + b1, LN, relu, @w2.T + b2 ============
    #pragma unroll 1
    for (int rr = 0; rr < 8; rr++) {
        const int r = w * 8 + rr;
        float a = 0.f;
        #pragma unroll 4
        for (int ch = 0; ch < 16; ch++) {
            const int j = ch * 128 + lane * 4;
            const float4 hv = *(const float4*)(sH + (j >> 5) * HP + (j & 31));
            const float4 wv = *(const float4*)(w1 + (size_t)r * 2048 + j);
            a = fmaf(wv.x, hv.x, fmaf(wv.y, hv.y,
                fmaf(wv.z, hv.z, fmaf(wv.w, hv.w, a))));
        }
        #pragma unroll
        for (int off = 16; off; off >>= 1) a += __shfl_xor_sync(0xffffffffu, a, off);
        if (lane == 0) sZ[r] = a + __ldg(b1 + r);
    }
    __syncthreads();
    if (w == 0) {
        float zv[4];
        #pragma unroll
        for (int qq = 0; qq < 4; qq++) zv[qq] = sZ[lane + 32 * qq];
        float s1 = zv[0] + zv[1] + zv[2] + zv[3];
        float s2 = zv[0] * zv[0] + zv[1] * zv[1] + zv[2] * zv[2] + zv[3] * zv[3];
        #pragma unroll
        for (int off = 16; off; off >>= 1) {
            s1 += __shfl_xor_sync(0xffffffffu, s1, off);
            s2 += __shfl_xor_sync(0xffffffffu, s2, off);
        }
        const float mu  = s1 * (1.f / 128.f);
        const float var = s2 * (1.f / 128.f) - mu * mu;
        const float rs  = __fdividef(1.f, sqrtf(var + 1e-5f));
        float o0 = 0.f, o1 = 0.f;
        #pragma unroll
        for (int qq = 0; qq < 4; qq++) {
            const int r = lane + 32 * qq;
            float zn = (zv[qq] - mu) * rs * __ldg(ln_g + r) + __ldg(ln_b + r);
            zn = fmaxf(zn, 0.f);
            o0 = fmaf(zn, __ldg(w2 + r), o0);
            o1 = fmaf(zn, __ldg(w2 + 128 + r), o1);
        }
        #pragma unroll
        for (int off = 16; off; off >>= 1) {
            o0 += __shfl_xor_sync(0xffffffffu, o0, off);
            o1 += __shfl_xor_sync(0xffffffffu, o1, off);
        }
        if (lane == 0) {
            out[b * 2 + 0] = o0 + __ldg(b2 + 0);
            out[b * 2 + 1] = o1 + __ldg(b2 + 1);
        }
    }
}

extern "C" void kernel_launch(void* const* d_in, const int* in_sizes, int n_in,
                              void* d_out, int out_size) {
    const int*   x      = (const int*)  d_in[0];
    const float* emb    = (const float*)d_in[1];
    const float* gate_w = (const float*)d_in[2];
    const float* gate_b = (const float*)d_in[3];
    const float* w1     = (const float*)d_in[4];
    const float* b1     = (const float*)d_in[5];
    const float* ln_g   = (const float*)d_in[6];
    const float* ln_b   = (const float*)d_in[7];
    const float* w2     = (const float*)d_in[8];
    const float* b2     = (const float*)d_in[9];
    const float* gp     = (const float*)d_in[10];
    float* out = (float*)d_out;

    setup_kernel<<<1, 256>>>(emb, gate_w, gate_b, gp);

    const int smem_bytes = SMEM_FLOATS * 4;
    cudaFuncSetAttribute(versor_main_kernel,
                         cudaFuncAttributeMaxDynamicSharedMemorySize, smem_bytes);
    versor_main_kernel<<<BB, NT, smem_bytes>>>(x, w1, b1, ln_g, ln_b, w2, b2, out);
}

// round 17
// speedup vs baseline: 1.1098x; 1.0610x over previous
#include <cuda_runtime.h>
#include <cuda_fp16.h>
#include <math.h>

#define BB 128
#define TT 512
#define GW_STRIDE 2080
#define NT 512

// gate row partition: [0,768) registers fp16, [768,2048) SMEM fp16
#define RROWS 768
#define SBASE 768
#define SROWS 1280
#define HP 36                     // padded h row stride (floats)

// SMEM float offsets (sW16 = 1280*64 halves = 40960 floats)
#define OFF_H  40960              // h state [64][36] fp32
#define OFF_HD 43264              // duplicated half2 h [2048]
#define OFF_A  45312              // 4x32x32 fp32
#define OFF_P  49408              // fp16 partials [16][72] halves
#define OFF_GR 49984              // 4x64
#define OFF_X  50240              // 512 ints
#define SMEM_FLOATS 50752         // 203008 bytes

__device__ float  d_A[4096];          // A[c][j][k]
__device__ float  d_gr[256];          // gate_b + r-term, [c][d]
__device__ __half d_gw16[2048 * 64];  // transposed fp16 weights [j][d]

static __device__ __forceinline__ unsigned long long pk2(float a, float b) {
    unsigned long long r; asm("mov.b64 %0, {%1,%2};" : "=l"(r) : "f"(a), "f"(b)); return r;
}
static __device__ __forceinline__ void ffma2(unsigned long long& d,
                                             unsigned long long a, unsigned long long b) {
    asm("fma.rn.f32x2 %0, %1, %2, %0;" : "+l"(d) : "l"(a), "l"(b));
}
static __device__ __forceinline__ float2 upk2(unsigned long long v) {
    float lo, hi; asm("mov.b64 {%0,%1}, %2;" : "=f"(lo), "=f"(hi) : "l"(v));
    return make_float2(lo, hi);
}
static __device__ __forceinline__ unsigned h2u(__half2 h) { return *(unsigned*)&h; }
static __device__ __forceinline__ __half2 u2h(unsigned u) { return *(__half2*)&u; }

// Parallel setup: 128 blocks x 256 threads.
// Every block computes r in SMEM. Blocks 0-15: d_A. Block 16: d_gr.
// All blocks: slice of the weight transpose (coalesced reads along j).
__global__ void setup_kernel(const float* __restrict__ emb,
                             const float* __restrict__ gate_w,
                             const float* __restrict__ gate_b,
                             const float* __restrict__ gp) {
    __shared__ float r[4][32];
    const int t   = threadIdx.x;           // 256 threads
    const int bid = blockIdx.x;            // 128 blocks
    if (t < 128) {
        int c = t >> 5, i = t & 31;
        float v = emb[c * 32 + i];
        float s = v * v;
        #pragma unroll
        for (int off = 16; off; off >>= 1) s += __shfl_xor_sync(0xffffffffu, s, off);
        r[c][i] = v / (sqrtf(s) + 1e-8f);
    }
    __syncthreads();

    if (bid < 16) {
        // d_A entries [bid*256 + t]
        const int idx = bid * 256 + t;
        const int cc = idx >> 10, jk = idx & 1023;
        float acc = 0.f;
        #pragma unroll
        for (int ii = 0; ii < 32; ii++) acc += r[cc][ii] * __ldg(gp + ii * 1024 + jk);
        d_A[idx] = acc;
    } else if (bid == 16) {
        // d_gr: 256 entries, one per thread
        const int cc = t >> 6, d = t & 63;
        float acc = gate_b[d];
        #pragma unroll
        for (int ii = 0; ii < 32; ii++)
            acc += __ldg(gate_w + (size_t)d * GW_STRIDE + 2048 + ii) * r[cc][ii];
        d_gr[t] = acc;
    }

    // transpose slice: 131072 elements over 128 blocks = 1024 each (4/thread)
    // idx -> d = idx >> 11, j = idx & 2047 : reads coalesced along j
    for (int q = 0; q < 4; q++) {
        const int idx = (bid * 1024) + q * 256 + t;
        const int d = idx >> 11, j = idx & 2047;
        d_gw16[(size_t)j * 64 + d] =
            __float2half_rn(__ldg(gate_w + (size_t)d * GW_STRIDE + j));
    }
}

__global__ void __launch_bounds__(NT, 1)
versor_main_kernel(const int* __restrict__ x,
                   const float* __restrict__ w1, const float* __restrict__ b1,
                   const float* __restrict__ ln_g, const float* __restrict__ ln_b,
                   const float* __restrict__ w2, const float* __restrict__ b2,
                   float* __restrict__ out) {
    extern __shared__ float sm[];
    __half*  sW16 = (__half*)sm;              // [1280][64] fp16 (local row = j-768)
    float*   sH   = sm + OFF_H;               // h state [64][HP]
    __half2* sHd  = (__half2*)(sm + OFF_HD);  // duplicated (h,h), 2048 rows
    float*   sA   = sm + OFF_A;
    __half*  sPh  = (__half*)(sm + OFF_P);    // fp16 partials [16][72]
    float*   sGr  = sm + OFF_GR;
    int*     sX   = (int*)(sm + OFF_X);
    float*   sZ   = sm + OFF_P;               // head alias (after loop)

    const int tid  = threadIdx.x;
    const int lane = tid & 31;
    const int w    = tid >> 5;                // warp 0..15
    const int jway = lane >> 3;               // 0..3
    const int oct  = lane & 7;                // d-octet
    const int b    = blockIdx.x;
    const int grp  = w * 4 + jway;            // row group 0..63

    // ---- init SMEM ----
    for (int idx = tid; idx < SROWS * 8; idx += NT)   // 1280*64 halves as uint4
        ((uint4*)sW16)[idx] = ((const uint4*)(d_gw16 + SBASE * 64))[idx];
    for (int idx = tid; idx < 4096; idx += NT) sA[idx] = d_A[idx];
    for (int idx = tid; idx < 256;  idx += NT) sGr[idx] = d_gr[idx];
    for (int idx = tid; idx < TT;   idx += NT) sX[idx] = x[b * TT + idx];
    for (int idx = tid; idx < 64 * HP; idx += NT)
        sH[idx] = ((idx % HP) == 0) ? 1.f : 0.f;
    for (int idx = tid; idx < 2048; idx += NT)
        sHd[idx] = __floats2half2_rn(((idx & 31) == 0) ? 1.f : 0.f,
                                     ((idx & 31) == 0) ? 1.f : 0.f);

    // ---- register fp16 weights: rows [0,768), 12 j x 8 d(4 half2)/thread ----
    unsigned wreg[48];
    {
        const int jb = grp * 12;
        #pragma unroll
        for (int jj = 0; jj < 12; jj++) {
            const uint4 v = *(const uint4*)(d_gw16 + (size_t)(jb + jj) * 64 + oct * 8);
            wreg[4 * jj + 0] = v.x; wreg[4 * jj + 1] = v.y;
            wreg[4 * jj + 2] = v.z; wreg[4 * jj + 3] = v.w;
        }
    }
    __syncthreads();

    const int dB = tid >> 3;              // phase-B versor (warp-exclusive row)
    const int s8 = tid & 7;               // 8-thread subgroup within versor
    const int k0 = s8 * 4;                // phase-B blade quad
    const __half2 hz = __float2half2_rn(0.f);

    int c = sX[0];
    #pragma unroll 1
    for (int t = 0; t < TT; t++) {
        const int c_next = (t + 1 < TT) ? sX[t + 1] : 0;

        // ============ Phase A: gate partial dots (all HFMA2, octet-d) ============
        __half2 ha0 = hz, ha1 = hz, ha2 = hz, ha3 = hz;
        // register rows (12), hj via 3 x LDS.128 on dup array
        {
            const int jb = grp * 12;
            #pragma unroll
            for (int q = 0; q < 3; q++) {
                const uint4 hq = *(const uint4*)(sHd + jb + 4 * q);
                const __half2 h0 = u2h(hq.x), h1 = u2h(hq.y);
                const __half2 h2 = u2h(hq.z), h3 = u2h(hq.w);
                ha0 = __hfma2(u2h(wreg[16 * q + 0]),  h0, ha0);
                ha1 = __hfma2(u2h(wreg[16 * q + 1]),  h0, ha1);
                ha2 = __hfma2(u2h(wreg[16 * q + 2]),  h0, ha2);
                ha3 = __hfma2(u2h(wreg[16 * q + 3]),  h0, ha3);
                ha0 = __hfma2(u2h(wreg[16 * q + 4]),  h1, ha0);
                ha1 = __hfma2(u2h(wreg[16 * q + 5]),  h1, ha1);
                ha2 = __hfma2(u2h(wreg[16 * q + 6]),  h1, ha2);
                ha3 = __hfma2(u2h(wreg[16 * q + 7]),  h1, ha3);
                ha0 = __hfma2(u2h(wreg[16 * q + 8]),  h2, ha0);
                ha1 = __hfma2(u2h(wreg[16 * q + 9]),  h2, ha1);
                ha2 = __hfma2(u2h(wreg[16 * q + 10]), h2, ha2);
                ha3 = __hfma2(u2h(wreg[16 * q + 11]), h2, ha3);
                ha0 = __hfma2(u2h(wreg[16 * q + 12]), h3, ha0);
                ha1 = __hfma2(u2h(wreg[16 * q + 13]), h3, ha1);
                ha2 = __hfma2(u2h(wreg[16 * q + 14]), h3, ha2);
                ha3 = __hfma2(u2h(wreg[16 * q + 15]), h3, ha3);
            }
        }
        // SMEM rows (20): local rows [grp*20, grp*20+20)
        {
            const int rb = grp * 20;
            #pragma unroll
            for (int q = 0; q < 5; q++) {
                const uint4 hq = *(const uint4*)(sHd + SBASE + rb + 4 * q);
                const __half2 hh[4] = { u2h(hq.x), u2h(hq.y), u2h(hq.z), u2h(hq.w) };
                #pragma unroll
                for (int rr = 0; rr < 4; rr++) {
                    const uint4 wv = ((const uint4*)sW16)[(rb + 4 * q + rr) * 8 + oct];
                    ha0 = __hfma2(u2h(wv.x), hh[rr], ha0);
                    ha1 = __hfma2(u2h(wv.y), hh[rr], ha1);
                    ha2 = __hfma2(u2h(wv.z), hh[rr], ha2);
                    ha3 = __hfma2(u2h(wv.w), hh[rr], ha3);
                }
            }
        }
        // reduce across the 4 jways, store RAW fp16 partials (1 STS.128, no cvt)
        {
            #pragma unroll
            for (int off = 8; off <= 16; off <<= 1) {
                ha0 = __hadd2(ha0, u2h(__shfl_xor_sync(0xffffffffu, h2u(ha0), off)));
                ha1 = __hadd2(ha1, u2h(__shfl_xor_sync(0xffffffffu, h2u(ha1), off)));
                ha2 = __hadd2(ha2, u2h(__shfl_xor_sync(0xffffffffu, h2u(ha2), off)));
                ha3 = __hadd2(ha3, u2h(__shfl_xor_sync(0xffffffffu, h2u(ha3), off)));
            }
            if (jway == 0) {
                uint4 pk;
                pk.x = h2u(ha0); pk.y = h2u(ha1); pk.z = h2u(ha2); pk.w = h2u(ha3);
                *(uint4*)(sPh + w * 72 + oct * 8) = pk;
            }
        }

        // ---- geometric product (pre-barrier; h stable, rows warp-exclusive) ----
        unsigned long long n0 = 0ull, n1 = 0ull;
        float4 hq4;
        float gr0;
        {
            const float* hrow = sH + dB * HP;
            const ulonglong2* Ap = (const ulonglong2*)(sA + c * 1024) + s8;
            #pragma unroll
            for (int jq = 0; jq < 8; jq++) {
                const float4 hv = *(const float4*)(hrow + jq * 4);
                unsigned long long hp; ulonglong2 av;
                hp = pk2(hv.x, hv.x); av = Ap[(jq * 4 + 0) * 8];
                ffma2(n0, av.x, hp); ffma2(n1, av.y, hp);
                hp = pk2(hv.y, hv.y); av = Ap[(jq * 4 + 1) * 8];
                ffma2(n0, av.x, hp); ffma2(n1, av.y, hp);
                hp = pk2(hv.z, hv.z); av = Ap[(jq * 4 + 2) * 8];
                ffma2(n0, av.x, hp); ffma2(n1, av.y, hp);
                hp = pk2(hv.w, hv.w); av = Ap[(jq * 4 + 3) * 8];
                ffma2(n0, av.x, hp); ffma2(n1, av.y, hp);
            }
            hq4 = *(const float4*)(hrow + k0);
            gr0 = sGr[c * 64 + dB];   // hoisted off the post-barrier tail
        }
        __syncthreads();   // barrier 1: partials visible; phase-A sHd reads done

        // ---- distributed gate reduce: 8 threads per versor ----
        float g;
        {
            float s = __half2float(sPh[(2 * s8) * 72 + dB])
                    + __half2float(sPh[(2 * s8 + 1) * 72 + dB]);
            s += __shfl_xor_sync(0xffffffffu, s, 1);
            s += __shfl_xor_sync(0xffffffffu, s, 2);
            s += __shfl_xor_sync(0xffffffffu, s, 4);
            s += gr0;
            g = __fdividef(1.f, 1.f + __expf(-s));
        }

        // ---- blend + normalize + store (fp32 state + dup-half2) ----
        {
            const float om = 1.f - g;
            const float2 na = upk2(n0);
            const float2 nb = upk2(n1);
            float4 v;
            v.x = om * hq4.x + g * na.x;
            v.y = om * hq4.y + g * na.y;
            v.z = om * hq4.z + g * nb.x;
            v.w = om * hq4.w + g * nb.y;
            float ss = v.x * v.x + v.y * v.y + v.z * v.z + v.w * v.w;
            ss += __shfl_xor_sync(0xffffffffu, ss, 1);
            ss += __shfl_xor_sync(0xffffffffu, ss, 2);
            ss += __shfl_xor_sync(0xffffffffu, ss, 4);
            const float sc = rsqrtf(ss + 1e-20f);
            v.x *= sc; v.y *= sc; v.z *= sc; v.w *= sc;
            *(float4*)(sH + dB * HP + k0) = v;
            uint4 pd;
            pd.x = h2u(__floats2half2_rn(v.x, v.x));
            pd.y = h2u(__floats2half2_rn(v.y, v.y));
            pd.z = h2u(__floats2half2_rn(v.z, v.z));
            pd.w = h2u(__floats2half2_rn(v.w, v.w));
            *(uint4*)(sHd + dB * 32 + k0) = pd;
        }
        c = c_next;
        __syncthreads();   // barrier 2: new h (fp32 + dup) visible
    }

    // ============ Head: z = h@w1.T + b1, LN, relu, @w2.T + b2 ============
    #pragma unroll 1
    for (int rr = 0; rr < 8; rr++) {
        const int r = w * 8 + rr;
        float a = 0.f;
        #pragma unroll 4
        for (int ch = 0; ch < 16; ch++) {
            const int j = ch * 128 + lane * 4;
            const float4 hv = *(const float4*)(sH + (j >> 5) * HP + (j & 31));
            const float4 wv = *(const float4*)(w1 + (size_t)r * 2048 + j);
            a = fmaf(wv.x, hv.x, fmaf(wv.y, hv.y,
                fmaf(wv.z, hv.z, fmaf(wv.w, hv.w, a))));
        }
        #pragma unroll
        for (int off = 16; off; off >>= 1) a += __shfl_xor_sync(0xffffffffu, a, off);
        if (lane == 0) sZ[r] = a + __ldg(b1 + r);
    }
    __syncthreads();
    if (w == 0) {
        float zv[4];
        #pragma unroll
        for (int qq = 0; qq < 4; qq++) zv[qq] = sZ[lane + 32 * qq];
        float s1 = zv[0] + zv[1] + zv[2] + zv[3];
        float s2 = zv[0] * zv[0] + zv[1] * zv[1] + zv[2] * zv[2] + zv[3] * zv[3];
        #pragma unroll
        for (int off = 16; off; off >>= 1) {
            s1 += __shfl_xor_sync(0xffffffffu, s1, off);
            s2 += __shfl_xor_sync(0xffffffffu, s2, off);
        }
        const float mu  = s1 * (1.f / 128.f);
        const float var = s2 * (1.f / 128.f) - mu * mu;
        const float rs  = __fdividef(1.f, sqrtf(var + 1e-5f));
        float o0 = 0.f, o1 = 0.f;
        #pragma unroll
        for (int qq = 0; qq < 4; qq++) {
            const int r = lane + 32 * qq;
            float zn = (zv[qq] - mu) * rs * __ldg(ln_g + r) + __ldg(ln_b + r);
            zn = fmaxf(zn, 0.f);
            o0 = fmaf(zn, __ldg(w2 + r), o0);
            o1 = fmaf(zn, __ldg(w2 + 128 + r), o1);
        }
        #pragma unroll
        for (int off = 16; off; off >>= 1) {
            o0 += __shfl_xor_sync(0xffffffffu, o0, off);
            o1 += __shfl_xor_sync(0xffffffffu, o1, off);
        }
        if (lane == 0) {
            out[b * 2 + 0] = o0 + __ldg(b2 + 0);
            out[b * 2 + 1] = o1 + __ldg(b2 + 1);
        }
    }
}

extern "C" void kernel_launch(void* const* d_in, const int* in_sizes, int n_in,
                              void* d_out, int out_size) {
    const int*   x      = (const int*)  d_in[0];
    const float* emb    = (const float*)d_in[1];
    const float* gate_w = (const float*)d_in[2];
    const float* gate_b = (const float*)d_in[3];
    const float* w1     = (const float*)d_in[4];
    const float* b1     = (const float*)d_in[5];
    const float* ln_g   = (const float*)d_in[6];
    const float* ln_b   = (const float*)d_in[7];
    const float* w2     = (const float*)d_in[8];
    const float* b2     = (const float*)d_in[9];
    const float* gp     = (const float*)d_in[10];
    float* out = (float*)d_out;

    setup_kernel<<<128, 256>>>(emb, gate_w, gate_b, gp);

    const int smem_bytes = SMEM_FLOATS * 4;
    cudaFuncSetAttribute(versor_main_kernel,
                         cudaFuncAttributeMaxDynamicSharedMemorySize, smem_bytes);
    versor_main_kernel<<<BB, NT, smem_bytes>>>(x, w1, b1, ln_g, ln_b, w2, b2, out);
}